// round 9
// baseline (speedup 1.0000x reference)
#include <cuda_runtime.h>
#include <math.h>

#define NBLK  148
#define NTHR  512
#define NW    16      // warps per block
#define MELWB 7       // mel warps per block   -> 148*7  = 1036 (1000 active)
#define DCWB  9       // dc/stop warps per blk -> 148*9  = 1332 (960 dc + 16 stop)

// problem shape (fixed by setup_inputs)
#define Bc    16
#define Tc    800
#define NMELc 80
#define Nc    3
#define Hc    4
#define Sc    160
#define Kc    5                        // Tc / Sc
#define NM4   20                       // NMELc / 4
#define MEL_QUADS (Bc*Tc*NMELc/4)      // 256000
#define MEL_WARPS 1000                 // 256000 / 256 quads-per-warp
#define DC_ROWS   (Nc*Bc*Hc*Sc)        // 30720 = 960 warps * 32
#define DC_WARPS  960
#define INV_MEL   (1.0 / (double)(Bc*Tc*NMELc))

__device__ double g_part[NBLK];
__device__ double g_stop_b[Bc];
__device__ int    g_cnt_b[Bc];
__device__ unsigned int g_done;

__global__ __launch_bounds__(NTHR)
void loss_kernel(const int* __restrict__ lengths,
                 const int* __restrict__ mask,          // JAX bool -> int32
                 const float* __restrict__ stop_pred,
                 const float4* __restrict__ mels_pred,
                 const float4* __restrict__ mels_target,
                 const float* __restrict__ align,
                 float* __restrict__ out)
{
    const int tid  = threadIdx.x;
    const int bid  = blockIdx.x;
    const int lane = tid & 31;
    const int warp = tid >> 5;

    __shared__ int s_len[Bc];
    if (tid < Bc) s_len[tid] = lengths[tid];
    __syncthreads();

    double mel_acc = 0.0, dc_acc = 0.0;

    if (warp < MELWB) {
        // ---- mel L1: each active warp covers 256 consecutive quads,
        //      8 lane-interleaved float4-pairs, all loads front-batched ----
        const int mw = bid * MELWB + warp;
        if (mw < MEL_WARPS) {
            const int q0 = mw * 256 + lane;
            float4 p[8], g[8];
            float  m[8];
            #pragma unroll
            for (int j = 0; j < 8; j++) {
                const int q = q0 + j * 32;
                p[j] = __ldg(&mels_pred[q]);
                g[j] = __ldg(&mels_target[q]);
                m[j] = __ldg(&mask[(unsigned)q / NM4]) ? 1.0f : 0.0f;
            }
            float acc = 0.0f;
            #pragma unroll
            for (int j = 0; j < 8; j++) {
                acc += fabsf(fmaf(p[j].x, m[j], -g[j].x))
                     + fabsf(fmaf(p[j].y, m[j], -g[j].y))
                     + fabsf(fmaf(p[j].z, m[j], -g[j].z))
                     + fabsf(fmaf(p[j].w, m[j], -g[j].w));
            }
            mel_acc = (double)acc;
        }
    } else {
        const int dw = bid * DCWB + (warp - MELWB);
        if (dw < DC_WARPS) {
            // ---- dc band sum: one thread per (n,bh,s) row, <=6 LDG.128 ----
            const int r     = dw * 32 + lane;
            const int s     = r % Sc;
            const int plane = r / Sc;
            const int b     = (plane % (Bc * Hc)) % Bc;  // reshape (n,H,B): b = bh % B
            if (Tc >= s_len[b]) {                         // bmask
                const int t_lo = (s >= 50) ? ((s - 50) / Kc + 1) : 0;  // s < k*t+50
                int t_hi = (s + 50) / Kc + 1;                           // k*t-50 <= s
                if (t_hi > Tc) t_hi = Tc;
                const int q_lo = t_lo >> 2;
                const int q_hi = (t_hi + 3) >> 2;
                const float4* row = (const float4*)(align + (size_t)r * Tc);
                float4 v[6];
                #pragma unroll
                for (int j = 0; j < 6; j++) {
                    const int qq = q_lo + j;
                    v[j] = (qq < q_hi) ? __ldg(&row[qq]) : make_float4(0.f,0.f,0.f,0.f);
                }
                float acc = 0.0f;
                #pragma unroll
                for (int j = 0; j < 6; j++) {
                    const int t0 = (q_lo + j) << 2;
                    acc += ((t0     >= t_lo && t0     < t_hi) ? v[j].x : 0.0f)
                         + ((t0 + 1 >= t_lo && t0 + 1 < t_hi) ? v[j].y : 0.0f)
                         + ((t0 + 2 >= t_lo && t0 + 2 < t_hi) ? v[j].z : 0.0f)
                         + ((t0 + 3 >= t_lo && t0 + 3 < t_hi) ? v[j].w : 0.0f);
                }
                dc_acc = (double)acc;
            }
        } else if (dw < DC_WARPS + Bc) {
            // ---- stop BCE for batch row b: mask count + last-true index ----
            const int b = dw - DC_WARPS;
            int cnt = 0, maxi = -1;
            const int* mrow = mask + b * Tc;
            #pragma unroll 5
            for (int t = lane; t < Tc; t += 32)
                if (mrow[t]) { cnt++; maxi = t; }       // t increasing: lane-max = last true
            #pragma unroll
            for (int o = 16; o; o >>= 1) {
                cnt += __shfl_xor_sync(0xffffffffu, cnt, o);
                int m2 = __shfl_xor_sync(0xffffffffu, maxi, o);
                maxi = max(maxi, m2);
            }
            if (lane == 0) {
                const int idx = (maxi < 0) ? 0 : maxi;
                float lg = logf(stop_pred[b * Tc + idx]);
                if (lg < -100.0f) lg = -100.0f;
                g_cnt_b[b]  = cnt;
                g_stop_b[b] = (double)(-5.0f * lg);     // STOP_WEIGHT = 5
            }
        }
    }

    // ---- block reduction -> ONE pre-normalized partial, plain STG ----
    #pragma unroll
    for (int o = 16; o; o >>= 1) {
        mel_acc += __shfl_xor_sync(0xffffffffu, mel_acc, o);
        dc_acc  += __shfl_xor_sync(0xffffffffu, dc_acc,  o);
    }
    __shared__ double s_m[NW], s_d[NW];
    if (lane == 0) { s_m[warp] = mel_acc; s_d[warp] = dc_acc; }
    __syncthreads();
    if (tid == 0) {
        double tm = 0.0, td = 0.0;
        #pragma unroll
        for (int i = 0; i < NW; i++) { tm += s_m[i]; td += s_d[i]; }
        long long ls = 0;
        #pragma unroll
        for (int b = 0; b < Bc; b++) ls += s_len[b];
        // mel/(B*T*NMEL) - DC_STRENGTH * dc/(H*ls*N)
        g_part[bid] = tm * INV_MEL
                    - 1e-4 * td / ((double)Hc * (double)ls * (double)Nc);
    }

    // ---- last-block finalize ----
    __threadfence();
    __shared__ unsigned int s_last;
    if (tid == 0) {
        unsigned int prev = atomicAdd(&g_done, 1u);
        s_last = (prev == NBLK - 1) ? 1u : 0u;
    }
    __syncthreads();
    if (s_last && warp == 0) {
        __threadfence();
        volatile double* vp = g_part;
        double t = 0.0;
        for (int i = lane; i < NBLK; i += 32) t += vp[i];
        #pragma unroll
        for (int o = 16; o; o >>= 1)
            t += __shfl_xor_sync(0xffffffffu, t, o);
        if (lane == 0) {
            volatile double* vs = g_stop_b;
            volatile int*    vc = g_cnt_b;
            double ss = 0.0; long long mc = 0;
            #pragma unroll
            for (int b = 0; b < Bc; b++) { ss += vs[b]; mc += vc[b]; }
            out[0] = (float)(t + ss / (double)mc);
            g_done = 0u;
            __threadfence();
        }
    }
}

extern "C" void kernel_launch(void* const* d_in, const int* in_sizes, int n_in,
                              void* d_out, int out_size)
{
    const int*    lengths     = (const int*)d_in[0];
    const int*    mask        = (const int*)d_in[1];     // bool -> int32
    const float*  stop_pred   = (const float*)d_in[2];
    const float4* mels_pred   = (const float4*)d_in[3];
    const float4* mels_target = (const float4*)d_in[4];
    const float*  align       = (const float*)d_in[5];

    loss_kernel<<<NBLK, NTHR>>>(lengths, mask, stop_pred, mels_pred, mels_target,
                                align, (float*)d_out);
}

// round 10
// speedup vs baseline: 1.1575x; 1.1575x over previous
#include <cuda_runtime.h>
#include <math.h>

#define NTHR  256
#define MELB  500                       // mel blocks: 500*8 warps * 64 quads = 256000
#define DCBLK 120                       // dc blocks: 120*256 = 30720 rows
#define STOPB 2
#define NBLK  (MELB + DCBLK + STOPB)    // 622

// problem shape (fixed by setup_inputs)
#define Bc    16
#define Tc    800
#define NMELc 80
#define Nc    3
#define Hc    4
#define Sc    160
#define Kc    5                         // Tc / Sc
#define NM4   20                        // NMELc / 4

__device__ double g_mel, g_dc, g_stop;
__device__ int g_mask_cnt;
__device__ unsigned long long g_len_sum;
__device__ unsigned int g_done;

__global__ __launch_bounds__(NTHR)
void loss_kernel(const int* __restrict__ lengths,
                 const int* __restrict__ mask,          // JAX bool -> int32
                 const float* __restrict__ stop_pred,
                 const float4* __restrict__ mels_pred,
                 const float4* __restrict__ mels_target,
                 const float* __restrict__ align,
                 float* __restrict__ out)
{
    const int tid  = threadIdx.x;
    const int bid  = blockIdx.x;
    const int lane = tid & 31;
    const int warp = tid >> 5;

    double mel_acc = 0.0, dc_acc = 0.0;

    if (bid < MELB) {
        // ---- mel L1: each warp covers 64 consecutive quads; 2 float4-pairs
        //      per lane (19 live regs -> ptxas can keep all loads in flight) ----
        const int gw = bid * (NTHR / 32) + warp;
        const int q0 = gw * 64 + lane;
        const int q1 = q0 + 32;
        float4 p0 = __ldg(&mels_pred[q0]);
        float4 g0 = __ldg(&mels_target[q0]);
        float4 p1 = __ldg(&mels_pred[q1]);
        float4 g1 = __ldg(&mels_target[q1]);
        float  m0 = __ldg(&mask[(unsigned)q0 / NM4]) ? 1.0f : 0.0f;
        float  m1 = __ldg(&mask[(unsigned)q1 / NM4]) ? 1.0f : 0.0f;
        float acc = fabsf(fmaf(p0.x, m0, -g0.x)) + fabsf(fmaf(p0.y, m0, -g0.y))
                  + fabsf(fmaf(p0.z, m0, -g0.z)) + fabsf(fmaf(p0.w, m0, -g0.w))
                  + fabsf(fmaf(p1.x, m1, -g1.x)) + fabsf(fmaf(p1.y, m1, -g1.y))
                  + fabsf(fmaf(p1.z, m1, -g1.z)) + fabsf(fmaf(p1.w, m1, -g1.w));
        mel_acc = (double)acc;
    } else if (bid < MELB + DCBLK) {
        // ---- dc band sum: one thread per (n,bh,s) row; window width <= 20
        //      -> at most 6 float4 quads, predicated + edge-selected ----
        const int r     = (bid - MELB) * NTHR + tid;
        const int s     = r % Sc;
        const int plane = r / Sc;
        const int b     = (plane % (Bc * Hc)) % Bc;   // reshape (n,H,B): b = bh % B
        if (Tc >= __ldg(&lengths[b])) {                // bmask
            const int t_lo = (s >= 50) ? ((s - 50) / Kc + 1) : 0;  // s < k*t+50
            int t_hi = (s + 50) / Kc + 1;                           // k*t-50 <= s
            if (t_hi > Tc) t_hi = Tc;
            const int q_lo = t_lo >> 2;
            const int q_hi = (t_hi + 3) >> 2;
            const float4* row = (const float4*)(align + (size_t)r * Tc);
            float4 v[6];
            #pragma unroll
            for (int j = 0; j < 6; j++) {
                const int qq = q_lo + j;
                v[j] = (qq < q_hi) ? __ldg(&row[qq]) : make_float4(0.f,0.f,0.f,0.f);
            }
            float acc = 0.0f;
            #pragma unroll
            for (int j = 0; j < 6; j++) {
                const int t0 = (q_lo + j) << 2;
                acc += ((t0     >= t_lo && t0     < t_hi) ? v[j].x : 0.0f)
                     + ((t0 + 1 >= t_lo && t0 + 1 < t_hi) ? v[j].y : 0.0f)
                     + ((t0 + 2 >= t_lo && t0 + 2 < t_hi) ? v[j].z : 0.0f)
                     + ((t0 + 3 >= t_lo && t0 + 3 < t_hi) ? v[j].w : 0.0f);
            }
            dc_acc = (double)acc;
        }
    } else {
        // ---- stop BCE: one warp per batch row ----
        const int b = (bid - MELB - DCBLK) * (NTHR / 32) + warp;  // 0..15
        if (b < Bc) {
            int cnt = 0, maxi = -1;
            const int* mrow = mask + b * Tc;
            #pragma unroll 5
            for (int t = lane; t < Tc; t += 32)
                if (mrow[t]) { cnt++; maxi = t; }      // t increasing: lane-max = last true
            #pragma unroll
            for (int o = 16; o; o >>= 1) {
                cnt += __shfl_xor_sync(0xffffffffu, cnt, o);
                int m2 = __shfl_xor_sync(0xffffffffu, maxi, o);
                maxi = max(maxi, m2);
            }
            if (lane == 0) {
                atomicAdd(&g_mask_cnt, cnt);
                const int idx = (maxi < 0) ? 0 : maxi;
                float lg = logf(stop_pred[b * Tc + idx]);
                if (lg < -100.0f) lg = -100.0f;
                atomicAdd(&g_stop, (double)(-5.0f * lg));   // STOP_WEIGHT = 5
            }
        }
        if (bid == MELB + DCBLK && tid == 0) {
            unsigned long long ls = 0;
            #pragma unroll
            for (int b2 = 0; b2 < Bc; b2++) ls += (unsigned long long)__ldg(&lengths[b2]);
            atomicAdd(&g_len_sum, ls);
        }
    }

    // ---- block reduction -> at most 2 double atomics per block ----
    #pragma unroll
    for (int o = 16; o; o >>= 1) {
        mel_acc += __shfl_xor_sync(0xffffffffu, mel_acc, o);
        dc_acc  += __shfl_xor_sync(0xffffffffu, dc_acc,  o);
    }
    __shared__ double s_m[NTHR / 32], s_d[NTHR / 32];
    if (lane == 0) { s_m[warp] = mel_acc; s_d[warp] = dc_acc; }
    __syncthreads();
    if (tid == 0) {
        double tm = 0.0, td = 0.0;
        #pragma unroll
        for (int i = 0; i < NTHR / 32; i++) { tm += s_m[i]; td += s_d[i]; }
        if (tm != 0.0) atomicAdd(&g_mel, tm);
        if (td != 0.0) atomicAdd(&g_dc,  td);
    }

    // ---- last-block finalize (and reset for graph replay) ----
    __threadfence();
    __shared__ unsigned int s_last;
    if (tid == 0) {
        unsigned int prev = atomicAdd(&g_done, 1u);
        s_last = (prev == NBLK - 1) ? 1u : 0u;
    }
    __syncthreads();
    if (s_last && tid == 0) {
        double mel = atomicAdd(&g_mel, 0.0);
        double dc  = atomicAdd(&g_dc, 0.0);
        double st  = atomicAdd(&g_stop, 0.0);
        int    mc  = atomicAdd(&g_mask_cnt, 0);
        unsigned long long ls = atomicAdd(&g_len_sum, 0ull);

        double mel_loss  = mel / ((double)Bc * (double)Tc * (double)NMELc);
        double stop_loss = st / (double)mc;
        double dcv = dc / ((double)Hc * (double)ls * (double)Nc);
        out[0] = (float)(mel_loss + stop_loss - 1e-4 * dcv);  // DC_STRENGTH = 1e-4

        g_mel = 0.0; g_dc = 0.0; g_stop = 0.0;
        g_mask_cnt = 0; g_len_sum = 0ull; g_done = 0u;
        __threadfence();
    }
}

extern "C" void kernel_launch(void* const* d_in, const int* in_sizes, int n_in,
                              void* d_out, int out_size)
{
    const int*    lengths     = (const int*)d_in[0];
    const int*    mask        = (const int*)d_in[1];     // bool -> int32
    const float*  stop_pred   = (const float*)d_in[2];
    const float4* mels_pred   = (const float4*)d_in[3];
    const float4* mels_target = (const float4*)d_in[4];
    const float*  align       = (const float*)d_in[5];

    loss_kernel<<<NBLK, NTHR>>>(lengths, mask, stop_pred, mels_pred, mels_target,
                                align, (float*)d_out);
}

// round 11
// speedup vs baseline: 1.3459x; 1.1628x over previous
#include <cuda_runtime.h>
#include <math.h>

#define NTHR  256
#define MELB  500                       // mel blocks: 500*8 warps * 64 quads = 256000
#define DCBLK 120                       // dc blocks: 120*256 = 30720 rows
#define K2BLK 122                       // 120 dc + 2 stop blocks

// problem shape (fixed by setup_inputs)
#define Bc    16
#define Tc    800
#define NMELc 80
#define Nc    3
#define Hc    4
#define Sc    160
#define Kc    5                         // Tc / Sc
#define NM4   20                        // NMELc / 4

__device__ double g_mel, g_dc, g_stop;
__device__ int g_mask_cnt;
__device__ unsigned long long g_len_sum;

// ---------------------------------------------------------------- mel kernel
__global__ __launch_bounds__(NTHR)
void mel_kernel(const int* __restrict__ mask,
                const float4* __restrict__ mels_pred,
                const float4* __restrict__ mels_target)
{
    const int tid  = threadIdx.x;
    const int lane = tid & 31;
    const int warp = tid >> 5;

    // each warp covers 64 consecutive quads; 2 float4-pairs per lane
    const int gw = blockIdx.x * (NTHR / 32) + warp;
    const int q0 = gw * 64 + lane;
    const int q1 = q0 + 32;
    float4 p0 = __ldg(&mels_pred[q0]);
    float4 g0 = __ldg(&mels_target[q0]);
    float4 p1 = __ldg(&mels_pred[q1]);
    float4 g1 = __ldg(&mels_target[q1]);
    float  m0 = __ldg(&mask[(unsigned)q0 / NM4]) ? 1.0f : 0.0f;
    float  m1 = __ldg(&mask[(unsigned)q1 / NM4]) ? 1.0f : 0.0f;
    float acc = fabsf(fmaf(p0.x, m0, -g0.x)) + fabsf(fmaf(p0.y, m0, -g0.y))
              + fabsf(fmaf(p0.z, m0, -g0.z)) + fabsf(fmaf(p0.w, m0, -g0.w))
              + fabsf(fmaf(p1.x, m1, -g1.x)) + fabsf(fmaf(p1.y, m1, -g1.y))
              + fabsf(fmaf(p1.z, m1, -g1.z)) + fabsf(fmaf(p1.w, m1, -g1.w));

    // float warp reduce (30 cyc/step) -> float smem -> ONE double atomic
    #pragma unroll
    for (int o = 16; o; o >>= 1) acc += __shfl_xor_sync(0xffffffffu, acc, o);
    __shared__ float s_m[NTHR / 32];
    if (lane == 0) s_m[warp] = acc;
    __syncthreads();
    if (tid == 0) {
        float tm = 0.0f;
        #pragma unroll
        for (int i = 0; i < NTHR / 32; i++) tm += s_m[i];
        atomicAdd(&g_mel, (double)tm);
    }
}

// ------------------------------------------------------------ dc+stop kernel
__global__ __launch_bounds__(NTHR)
void dc_stop_kernel(const int* __restrict__ lengths,
                    const int* __restrict__ mask,
                    const float* __restrict__ stop_pred,
                    const float* __restrict__ align)
{
    const int tid  = threadIdx.x;
    const int bid  = blockIdx.x;
    const int lane = tid & 31;
    const int warp = tid >> 5;

    if (bid < DCBLK) {
        // dc band sum: one thread per (n,bh,s) row; window width <= 20
        const int r     = bid * NTHR + tid;
        const int s     = r % Sc;
        const int plane = r / Sc;
        const int b     = (plane % (Bc * Hc)) % Bc;    // reshape (n,H,B): b = bh % B
        float acc = 0.0f;
        if (Tc >= __ldg(&lengths[b])) {                 // bmask
            const int t_lo = (s >= 50) ? ((s - 50) / Kc + 1) : 0;   // s < k*t+50
            int t_hi = (s + 50) / Kc + 1;                            // k*t-50 <= s
            if (t_hi > Tc) t_hi = Tc;
            const int q_lo = t_lo >> 2;
            const int q_hi = (t_hi + 3) >> 2;
            const float4* row = (const float4*)(align + (size_t)r * Tc);
            float4 v[6];
            #pragma unroll
            for (int j = 0; j < 6; j++) {
                const int qq = q_lo + j;
                v[j] = (qq < q_hi) ? __ldg(&row[qq]) : make_float4(0.f,0.f,0.f,0.f);
            }
            #pragma unroll
            for (int j = 0; j < 6; j++) {
                const int t0 = (q_lo + j) << 2;
                acc += ((t0     >= t_lo && t0     < t_hi) ? v[j].x : 0.0f)
                     + ((t0 + 1 >= t_lo && t0 + 1 < t_hi) ? v[j].y : 0.0f)
                     + ((t0 + 2 >= t_lo && t0 + 2 < t_hi) ? v[j].z : 0.0f)
                     + ((t0 + 3 >= t_lo && t0 + 3 < t_hi) ? v[j].w : 0.0f);
            }
        }
        #pragma unroll
        for (int o = 16; o; o >>= 1) acc += __shfl_xor_sync(0xffffffffu, acc, o);
        __shared__ float s_d[NTHR / 32];
        if (lane == 0) s_d[warp] = acc;
        __syncthreads();
        if (tid == 0) {
            float td = 0.0f;
            #pragma unroll
            for (int i = 0; i < NTHR / 32; i++) td += s_d[i];
            atomicAdd(&g_dc, (double)td);
        }
    } else {
        // stop BCE: one warp per batch row (blocks DCBLK, DCBLK+1)
        const int b = (bid - DCBLK) * (NTHR / 32) + warp;   // 0..15
        if (b < Bc) {
            int cnt = 0, maxi = -1;
            const int* mrow = mask + b * Tc;
            #pragma unroll 5
            for (int t = lane; t < Tc; t += 32)
                if (mrow[t]) { cnt++; maxi = t; }       // t increasing: lane-max = last true
            #pragma unroll
            for (int o = 16; o; o >>= 1) {
                cnt += __shfl_xor_sync(0xffffffffu, cnt, o);
                int m2 = __shfl_xor_sync(0xffffffffu, maxi, o);
                maxi = max(maxi, m2);
            }
            if (lane == 0) {
                atomicAdd(&g_mask_cnt, cnt);
                const int idx = (maxi < 0) ? 0 : maxi;
                float lg = logf(stop_pred[b * Tc + idx]);
                if (lg < -100.0f) lg = -100.0f;
                atomicAdd(&g_stop, (double)(-5.0f * lg));   // STOP_WEIGHT = 5
            }
        }
        if (bid == DCBLK && tid == 0) {
            unsigned long long ls = 0;
            #pragma unroll
            for (int b2 = 0; b2 < Bc; b2++) ls += (unsigned long long)__ldg(&lengths[b2]);
            atomicAdd(&g_len_sum, ls);
        }
    }
}

// ------------------------------------------------------------ finalize kernel
__global__ void finalize_kernel(float* __restrict__ out)
{
    if (threadIdx.x == 0) {
        double mel = g_mel, dc = g_dc, st = g_stop;
        int    mc  = g_mask_cnt;
        unsigned long long ls = g_len_sum;

        double mel_loss  = mel / ((double)Bc * (double)Tc * (double)NMELc);
        double stop_loss = st / (double)mc;
        double dcv = dc / ((double)Hc * (double)ls * (double)Nc);
        out[0] = (float)(mel_loss + stop_loss - 1e-4 * dcv);  // DC_STRENGTH = 1e-4

        // reset for next replay (prior kernels of the next replay start clean)
        g_mel = 0.0; g_dc = 0.0; g_stop = 0.0;
        g_mask_cnt = 0; g_len_sum = 0ull;
    }
}

extern "C" void kernel_launch(void* const* d_in, const int* in_sizes, int n_in,
                              void* d_out, int out_size)
{
    const int*    lengths     = (const int*)d_in[0];
    const int*    mask        = (const int*)d_in[1];     // bool -> int32
    const float*  stop_pred   = (const float*)d_in[2];
    const float4* mels_pred   = (const float4*)d_in[3];
    const float4* mels_target = (const float4*)d_in[4];
    const float*  align       = (const float*)d_in[5];

    mel_kernel<<<MELB, NTHR>>>(mask, mels_pred, mels_target);
    dc_stop_kernel<<<K2BLK, NTHR>>>(lengths, mask, stop_pred, align);
    finalize_kernel<<<1, 32>>>((float*)d_out);
}

// round 12
// speedup vs baseline: 1.3821x; 1.0269x over previous
#include <cuda_runtime.h>
#include <math.h>

#define NTHR  256
#define MELB  250                       // mel: 250 blocks * 8 warps * 128 quads = 256000
#define DCBLK 240                       // dc: 240 blocks * 256 thr = 61440 = 2 thr/row
#define NBLKB 242                       // 240 dc + 2 stop blocks

// problem shape (fixed by setup_inputs)
#define Bc    16
#define Tc    800
#define NMELc 80
#define Nc    3
#define Hc    4
#define Sc    160
#define Kc    5                         // Tc / Sc
#define NM4   20                        // NMELc / 4

__device__ double g_mel, g_dc, g_stop;
__device__ int g_mask_cnt;
__device__ unsigned long long g_len_sum;
__device__ unsigned int g_done;

// ---------------------------------------------------------------- mel kernel
__global__ __launch_bounds__(NTHR)
void mel_kernel(const int* __restrict__ mask,
                const float4* __restrict__ mels_pred,
                const float4* __restrict__ mels_target)
{
    const int tid  = threadIdx.x;
    const int lane = tid & 31;
    const int warp = tid >> 5;

    // each warp covers 128 consecutive quads; 4 lane-interleaved float4-pairs
    const int gw = blockIdx.x * (NTHR / 32) + warp;
    const int q0 = gw * 128 + lane;
    float4 p[4], g[4];
    float  m[4];
    #pragma unroll
    for (int j = 0; j < 4; j++) {
        const int q = q0 + j * 32;
        p[j] = __ldg(&mels_pred[q]);
        g[j] = __ldg(&mels_target[q]);
        m[j] = __ldg(&mask[(unsigned)q / NM4]) ? 1.0f : 0.0f;
    }
    float acc = 0.0f;
    #pragma unroll
    for (int j = 0; j < 4; j++) {
        acc += fabsf(fmaf(p[j].x, m[j], -g[j].x)) + fabsf(fmaf(p[j].y, m[j], -g[j].y))
             + fabsf(fmaf(p[j].z, m[j], -g[j].z)) + fabsf(fmaf(p[j].w, m[j], -g[j].w));
    }

    // float warp reduce -> float smem -> ONE double atomic per block
    #pragma unroll
    for (int o = 16; o; o >>= 1) acc += __shfl_xor_sync(0xffffffffu, acc, o);
    __shared__ float s_m[NTHR / 32];
    if (lane == 0) s_m[warp] = acc;
    __syncthreads();
    if (tid == 0) {
        float tm = 0.0f;
        #pragma unroll
        for (int i = 0; i < NTHR / 32; i++) tm += s_m[i];
        atomicAdd(&g_mel, (double)tm);
    }
}

// ---------------------------- dc + stop + finalize kernel (runs after mel) --
__global__ __launch_bounds__(NTHR)
void dc_stop_fin_kernel(const int* __restrict__ lengths,
                        const int* __restrict__ mask,
                        const float* __restrict__ stop_pred,
                        const float* __restrict__ align,
                        float* __restrict__ out)
{
    const int tid  = threadIdx.x;
    const int bid  = blockIdx.x;
    const int lane = tid & 31;
    const int warp = tid >> 5;

    if (bid < DCBLK) {
        // dc band sum: TWO threads per (n,bh,s) row, 3 quads each.
        // band[s,t] nonzero iff k*t-50 <= s < k*t+50 -> contiguous window <= 20
        // floats -> at most 6 float4 quads per row.
        const int gt   = bid * NTHR + tid;
        const int r    = gt >> 1;
        const int half = gt & 1;
        const int s     = r % Sc;
        const int plane = r / Sc;
        const int b     = (plane % (Bc * Hc)) % Bc;    // reshape (n,H,B): b = bh % B
        float acc = 0.0f;
        if (Tc >= __ldg(&lengths[b])) {                 // bmask
            const int t_lo = (s >= 50) ? ((s - 50) / Kc + 1) : 0;   // s < k*t+50
            int t_hi = (s + 50) / Kc + 1;                            // k*t-50 <= s
            if (t_hi > Tc) t_hi = Tc;
            const int q_lo = t_lo >> 2;
            const int q_hi = (t_hi + 3) >> 2;
            const float4* row = (const float4*)(align + (size_t)r * Tc);
            const int j0 = half * 3;
            float4 v[3];
            #pragma unroll
            for (int j = 0; j < 3; j++) {
                const int qq = q_lo + j0 + j;
                v[j] = (qq < q_hi) ? __ldg(&row[qq]) : make_float4(0.f,0.f,0.f,0.f);
            }
            #pragma unroll
            for (int j = 0; j < 3; j++) {
                const int t0 = (q_lo + j0 + j) << 2;
                acc += ((t0     >= t_lo && t0     < t_hi) ? v[j].x : 0.0f)
                     + ((t0 + 1 >= t_lo && t0 + 1 < t_hi) ? v[j].y : 0.0f)
                     + ((t0 + 2 >= t_lo && t0 + 2 < t_hi) ? v[j].z : 0.0f)
                     + ((t0 + 3 >= t_lo && t0 + 3 < t_hi) ? v[j].w : 0.0f);
            }
        }
        #pragma unroll
        for (int o = 16; o; o >>= 1) acc += __shfl_xor_sync(0xffffffffu, acc, o);
        __shared__ float s_d[NTHR / 32];
        if (lane == 0) s_d[warp] = acc;
        __syncthreads();
        if (tid == 0) {
            float td = 0.0f;
            #pragma unroll
            for (int i = 0; i < NTHR / 32; i++) td += s_d[i];
            atomicAdd(&g_dc, (double)td);
        }
    } else {
        // stop BCE: one warp per batch row (blocks DCBLK, DCBLK+1)
        const int b = (bid - DCBLK) * (NTHR / 32) + warp;   // 0..15
        if (b < Bc) {
            int cnt = 0, maxi = -1;
            const int* mrow = mask + b * Tc;
            #pragma unroll 5
            for (int t = lane; t < Tc; t += 32)
                if (mrow[t]) { cnt++; maxi = t; }       // t increasing: lane-max = last true
            #pragma unroll
            for (int o = 16; o; o >>= 1) {
                cnt += __shfl_xor_sync(0xffffffffu, cnt, o);
                int m2 = __shfl_xor_sync(0xffffffffu, maxi, o);
                maxi = max(maxi, m2);
            }
            if (lane == 0) {
                atomicAdd(&g_mask_cnt, cnt);
                const int idx = (maxi < 0) ? 0 : maxi;
                float lg = logf(stop_pred[b * Tc + idx]);
                if (lg < -100.0f) lg = -100.0f;
                atomicAdd(&g_stop, (double)(-5.0f * lg));   // STOP_WEIGHT = 5
            }
        }
        if (bid == DCBLK && tid == 0) {
            unsigned long long ls = 0;
            #pragma unroll
            for (int b2 = 0; b2 < Bc; b2++) ls += (unsigned long long)__ldg(&lengths[b2]);
            atomicAdd(&g_len_sum, ls);
        }
    }

    // ---- last-done block finalizes (g_mel is final: prior kernel in stream) ----
    __threadfence();
    __shared__ unsigned int s_last;
    if (tid == 0) {
        unsigned int prev = atomicAdd(&g_done, 1u);
        s_last = (prev == NBLKB - 1) ? 1u : 0u;
    }
    __syncthreads();
    if (s_last && tid == 0) {
        double mel = atomicAdd(&g_mel, 0.0);
        double dc  = atomicAdd(&g_dc, 0.0);
        double st  = atomicAdd(&g_stop, 0.0);
        int    mc  = atomicAdd(&g_mask_cnt, 0);
        unsigned long long ls = atomicAdd(&g_len_sum, 0ull);

        double mel_loss  = mel / ((double)Bc * (double)Tc * (double)NMELc);
        double stop_loss = st / (double)mc;
        double dcv = dc / ((double)Hc * (double)ls * (double)Nc);
        out[0] = (float)(mel_loss + stop_loss - 1e-4 * dcv);  // DC_STRENGTH = 1e-4

        g_mel = 0.0; g_dc = 0.0; g_stop = 0.0;
        g_mask_cnt = 0; g_len_sum = 0ull; g_done = 0u;
        __threadfence();
    }
}

extern "C" void kernel_launch(void* const* d_in, const int* in_sizes, int n_in,
                              void* d_out, int out_size)
{
    const int*    lengths     = (const int*)d_in[0];
    const int*    mask        = (const int*)d_in[1];     // bool -> int32
    const float*  stop_pred   = (const float*)d_in[2];
    const float4* mels_pred   = (const float4*)d_in[3];
    const float4* mels_target = (const float4*)d_in[4];
    const float*  align       = (const float*)d_in[5];

    mel_kernel<<<MELB, NTHR>>>(mask, mels_pred, mels_target);
    dc_stop_fin_kernel<<<NBLKB, NTHR>>>(lengths, mask, stop_pred, align, (float*)d_out);
}